// round 1
// baseline (speedup 1.0000x reference)
#include <cuda_runtime.h>
#include <cstdint>

#define DEV_INLINE __device__ __forceinline__

// ---------------- problem constants ----------------
constexpr int Bb = 16, Cc = 512, Ll = 2048, Hh = 8, Dh = 64;
constexpr int T  = Bb * Ll;      // 32768 tokens
constexpr int C2 = 2 * Cc;       // 1024
constexpr float EPS = 1e-5f;

// ---------------- scratch (device globals; no allocation allowed) ----------------
__device__ __align__(256) float g_qr [T * Cc];        // q pre-rounded to tf32 (B,C,L)
__device__ __align__(256) float g_hn [Bb * Cc * Ll];  // normalized x (B,C,L), tf32-rounded
__device__ __align__(256) float g_Q  [T * Cc];
__device__ __align__(256) float g_K  [T * Cc];
__device__ __align__(256) float g_V  [T * Cc];
__device__ __align__(256) float g_o  [T * Cc];        // attention out (token-major), tf32-rounded
__device__ __align__(256) float g_op [T * Cc];        // o @ Wo + bo (token-major)
__device__ __align__(256) float g_h2 [T * Cc];        // norm2(op), tf32-rounded
__device__ __align__(256) float g_u  [T * C2];        // gelu(fc), tf32-rounded
__device__ __align__(256) float g_m  [T * Cc];        // pr output (token-major)
__device__ __align__(256) float g_mean1[Bb * Cc];
__device__ __align__(256) float g_rstd1[Bb * Cc];
__device__ __align__(256) float g_mean2[Bb * Cc];
__device__ __align__(256) float g_rstd2[Bb * Cc];
__device__ __align__(256) float g_p1 [Bb * 16 * Cc];
__device__ __align__(256) float g_p2 [Bb * 16 * Cc];
__device__ __align__(256) float g_Wq [Cc * Cc];
__device__ __align__(256) float g_Wk [Cc * Cc];
__device__ __align__(256) float g_Wv [Cc * Cc];
__device__ __align__(256) float g_Wo [Cc * Cc];
__device__ __align__(256) float g_Wfc[Cc * C2];
__device__ __align__(256) float g_Wpr[C2 * Cc];

// ---------------- small helpers ----------------
DEV_INLINE float to_tf32(float x) {
    unsigned u;
    asm("cvt.rna.tf32.f32 %0, %1;" : "=r"(u) : "f"(x));
    return __uint_as_float(u);
}

DEV_INLINE void cp16(float* dst, const float* src) {
    unsigned d = (unsigned)__cvta_generic_to_shared(dst);
    asm volatile("cp.async.cg.shared.global [%0], [%1], 16;" :: "r"(d), "l"(src));
}
DEV_INLINE void cp_commit() { asm volatile("cp.async.commit_group;"); }

DEV_INLINE void mma_tf32(float d[4], float a0, float a1, float a2, float a3,
                         float b0, float b1) {
    asm volatile(
        "mma.sync.aligned.m16n8k8.row.col.f32.tf32.tf32.f32 "
        "{%0,%1,%2,%3}, {%4,%5,%6,%7}, {%8,%9}, {%0,%1,%2,%3};"
        : "+f"(d[0]), "+f"(d[1]), "+f"(d[2]), "+f"(d[3])
        : "r"(__float_as_uint(a0)), "r"(__float_as_uint(a1)),
          "r"(__float_as_uint(a2)), "r"(__float_as_uint(a3)),
          "r"(__float_as_uint(b0)), "r"(__float_as_uint(b1)));
}

// ---------------- elementwise tf32 rounding (weights, q) ----------------
__global__ void round4_kernel(const float* __restrict__ src, float* __restrict__ dst, int n4) {
    int i = blockIdx.x * blockDim.x + threadIdx.x;
    if (i >= n4) return;
    float4 v = ((const float4*)src)[i];
    v.x = to_tf32(v.x); v.y = to_tf32(v.y); v.z = to_tf32(v.z); v.w = to_tf32(v.w);
    ((float4*)dst)[i] = v;
}

// ---------------- instance-norm stats over L for (B,C,L) tensor ----------------
__global__ void stats1_kernel(const float* __restrict__ x,
                              float* __restrict__ mean, float* __restrict__ rstd) {
    int row = blockIdx.x;  // b*C + c
    const float4* p = (const float4*)(x + (size_t)row * Ll);
    float s = 0.f, s2 = 0.f;
    for (int i = threadIdx.x; i < Ll / 4; i += blockDim.x) {
        float4 v = p[i];
        s  += v.x + v.y + v.z + v.w;
        s2 += v.x * v.x + v.y * v.y + v.z * v.z + v.w * v.w;
    }
    #pragma unroll
    for (int o = 16; o; o >>= 1) {
        s  += __shfl_xor_sync(0xffffffffu, s,  o);
        s2 += __shfl_xor_sync(0xffffffffu, s2, o);
    }
    __shared__ float ws[8], ws2[8];
    int w = threadIdx.x >> 5;
    if ((threadIdx.x & 31) == 0) { ws[w] = s; ws2[w] = s2; }
    __syncthreads();
    if (threadIdx.x == 0) {
        float a = 0.f, b = 0.f;
        #pragma unroll
        for (int i = 0; i < 8; i++) { a += ws[i]; b += ws2[i]; }
        float mu  = a / (float)Ll;
        float var = b / (float)Ll - mu * mu;
        mean[row] = mu;
        rstd[row] = rsqrtf(var + EPS);
    }
}

// normalize x (B,C,L) -> hn (same layout), tf32-rounded
__global__ void norm1_kernel(const float* __restrict__ x, const float* __restrict__ mean,
                             const float* __restrict__ rstd, const float* __restrict__ g,
                             const float* __restrict__ be, float* __restrict__ out) {
    int i  = blockIdx.x * blockDim.x + threadIdx.x;   // over B*C*L/4
    int bc = i / (Ll / 4);
    int c  = bc % Cc;
    float mu = mean[bc];
    float rs = rstd[bc] * g[c];
    float bv = be[c];
    float4 v = ((const float4*)x)[i];
    v.x = to_tf32((v.x - mu) * rs + bv);
    v.y = to_tf32((v.y - mu) * rs + bv);
    v.z = to_tf32((v.z - mu) * rs + bv);
    v.w = to_tf32((v.w - mu) * rs + bv);
    ((float4*)out)[i] = v;
}

// ---------------- GEMM: out[t, n] = sum_k A[t,k] * W[k,n] + bias[n] ----------------
// AMODE 0: A token-major  (T x Cin)
// AMODE 1: A channel-major (B, Cin, L)  [k = channel]
constexpr int BM = 128, BN = 128, BK = 16;
constexpr int SA_T = BK + 4;   // 20  (m-major A smem stride)
constexpr int SA_C = BM + 8;   // 136 (k-major A smem stride)
constexpr int SB   = BN + 8;   // 136

template<int AMODE, bool GELU, bool ROUND>
__global__ __launch_bounds__(256, 2)
void gemm_kernel(const float* __restrict__ A, const float* __restrict__ W,
                 const float* __restrict__ bias, float* __restrict__ out,
                 int Cin, int Cout) {
    constexpr int ASTG = (AMODE == 0) ? BM * SA_T : BK * SA_C;
    __shared__ float As[2][ASTG];
    __shared__ float Bs[2][BK * SB];

    int tid  = threadIdx.x;
    int t0   = blockIdx.y * BM;
    int n0   = blockIdx.x * BN;
    int lane = tid & 31, warp = tid >> 5;
    int wm = warp & 3, wn = warp >> 2;       // 4 x 2 warp grid, warp tile 32x64
    int gid = lane >> 2, tig = lane & 3;

    int bidx = t0 / Ll, l0 = t0 % Ll;        // for CHAN mode (BM divides L)

    auto loadA = [&](int kb, int s) {
        if (AMODE == 0) {
            #pragma unroll
            for (int it = 0; it < 2; it++) {
                int idx = tid + it * 256;
                int m = idx >> 2, q = (idx & 3) << 2;
                cp16(&As[s][m * SA_T + q], A + (size_t)(t0 + m) * Cin + kb + q);
            }
        } else {
            #pragma unroll
            for (int it = 0; it < 2; it++) {
                int c = (tid >> 5) + it * 8;
                int l = (tid & 31) << 2;
                cp16(&As[s][c * SA_C + l],
                     A + ((size_t)bidx * Cin + kb + c) * Ll + l0 + l);
            }
        }
    };
    auto loadB = [&](int kb, int s) {
        #pragma unroll
        for (int it = 0; it < 2; it++) {
            int idx = tid + it * 256;
            int c = idx >> 5, nq = (idx & 31) << 2;
            cp16(&Bs[s][c * SB + nq], W + (size_t)(kb + c) * Cout + n0 + nq);
        }
    };

    float acc[2][8][4];
    #pragma unroll
    for (int i = 0; i < 2; i++)
        #pragma unroll
        for (int j = 0; j < 8; j++)
            #pragma unroll
            for (int k = 0; k < 4; k++) acc[i][j][k] = 0.f;

    int nk = Cin / BK;
    loadA(0, 0); loadB(0, 0); cp_commit();

    for (int kb = 0; kb < nk; kb++) {
        int cur = kb & 1;
        if (kb + 1 < nk) {
            loadA((kb + 1) * BK, cur ^ 1);
            loadB((kb + 1) * BK, cur ^ 1);
            cp_commit();
            asm volatile("cp.async.wait_group 1;");
        } else {
            asm volatile("cp.async.wait_group 0;");
        }
        __syncthreads();

        const float* A_s = As[cur];
        const float* B_s = Bs[cur];
        #pragma unroll
        for (int kk = 0; kk < BK; kk += 8) {
            float bf[8][2];
            #pragma unroll
            for (int j = 0; j < 8; j++) {
                int nn = wn * 64 + j * 8 + gid;
                bf[j][0] = B_s[(kk + tig) * SB + nn];
                bf[j][1] = B_s[(kk + tig + 4) * SB + nn];
            }
            #pragma unroll
            for (int i = 0; i < 2; i++) {
                int mm = wm * 32 + i * 16 + gid;
                float a0, a1, a2, a3;
                if (AMODE == 0) {
                    a0 = A_s[mm * SA_T + kk + tig];
                    a2 = A_s[mm * SA_T + kk + tig + 4];
                    a1 = A_s[(mm + 8) * SA_T + kk + tig];
                    a3 = A_s[(mm + 8) * SA_T + kk + tig + 4];
                } else {
                    a0 = A_s[(kk + tig) * SA_C + mm];
                    a1 = A_s[(kk + tig) * SA_C + mm + 8];
                    a2 = A_s[(kk + tig + 4) * SA_C + mm];
                    a3 = A_s[(kk + tig + 4) * SA_C + mm + 8];
                }
                #pragma unroll
                for (int j = 0; j < 8; j++)
                    mma_tf32(acc[i][j], a0, a1, a2, a3, bf[j][0], bf[j][1]);
            }
        }
        __syncthreads();
    }

    // epilogue
    #pragma unroll
    for (int i = 0; i < 2; i++) {
        #pragma unroll
        for (int j = 0; j < 8; j++) {
            int gr = t0 + wm * 32 + i * 16 + gid;
            int gc = n0 + wn * 64 + j * 8 + tig * 2;
            float b0 = bias[gc], b1 = bias[gc + 1];
            float v0 = acc[i][j][0] + b0;
            float v1 = acc[i][j][1] + b1;
            float v2 = acc[i][j][2] + b0;
            float v3 = acc[i][j][3] + b1;
            if (GELU) {
                v0 = v0 / (1.f + expf(-1.702f * v0));
                v1 = v1 / (1.f + expf(-1.702f * v1));
                v2 = v2 / (1.f + expf(-1.702f * v2));
                v3 = v3 / (1.f + expf(-1.702f * v3));
            }
            if (ROUND) {
                v0 = to_tf32(v0); v1 = to_tf32(v1);
                v2 = to_tf32(v2); v3 = to_tf32(v3);
            }
            float2 w0; w0.x = v0; w0.y = v1;
            float2 w1; w1.x = v2; w1.y = v3;
            *(float2*)&out[(size_t)gr * Cout + gc]       = w0;
            *(float2*)&out[(size_t)(gr + 8) * Cout + gc] = w1;
        }
    }
}

// ---------------- windowed attention (KS=3), warp per (token, head) ----------------
__global__ void attn_kernel(const float* __restrict__ Q, const float* __restrict__ K,
                            const float* __restrict__ V, float* __restrict__ O) {
    int wid  = (blockIdx.x * blockDim.x + threadIdx.x) >> 5;
    int lane = threadIdx.x & 31;
    int t = wid >> 3;         // / H
    int h = wid & 7;
    int l = t & (Ll - 1);
    int base = t * Cc + h * Dh;

    float qa = Q[base + lane];
    float qb = Q[base + lane + 32];

    float sc[3];
    #pragma unroll
    for (int k = 0; k < 3; k++) {
        int pos = l + k - 1;
        bool valid = (pos >= 0) && (pos < Ll);
        float s = 0.f;
        if (valid) {
            int kb = base + (k - 1) * Cc;
            s = qa * K[kb + lane] + qb * K[kb + lane + 32];
        }
        #pragma unroll
        for (int o = 16; o; o >>= 1) s += __shfl_xor_sync(0xffffffffu, s, o);
        sc[k] = valid ? s * 0.125f : -1e9f;
    }
    float mx = fmaxf(sc[0], fmaxf(sc[1], sc[2]));
    float e0 = expf(sc[0] - mx), e1 = expf(sc[1] - mx), e2 = expf(sc[2] - mx);
    float inv = 1.f / (e0 + e1 + e2);
    float p[3] = {e0 * inv, e1 * inv, e2 * inv};

    float oa = 0.f, ob = 0.f;
    #pragma unroll
    for (int k = 0; k < 3; k++) {
        int pos = l + k - 1;
        if (pos >= 0 && pos < Ll) {
            int vb = base + (k - 1) * Cc;
            oa += p[k] * V[vb + lane];
            ob += p[k] * V[vb + lane + 32];
        }
    }
    O[base + lane]      = to_tf32(oa);
    O[base + lane + 32] = to_tf32(ob);
}

// ---------------- norm2 stats over L of token-major op ----------------
__global__ void stats2_part(const float* __restrict__ op,
                            float* __restrict__ p1, float* __restrict__ p2) {
    int chunk = blockIdx.x, b = blockIdx.y, c = threadIdx.x;
    int t0 = b * Ll + chunk * 128;
    float s = 0.f, s2 = 0.f;
    for (int l = 0; l < 128; l++) {
        float v = op[(size_t)(t0 + l) * Cc + c];
        s += v; s2 += v * v;
    }
    p1[(b * 16 + chunk) * Cc + c] = s;
    p2[(b * 16 + chunk) * Cc + c] = s2;
}

__global__ void stats2_fin(const float* __restrict__ p1, const float* __restrict__ p2,
                           float* __restrict__ mean, float* __restrict__ rstd) {
    int bc = blockIdx.x * blockDim.x + threadIdx.x;
    if (bc >= Bb * Cc) return;
    int b = bc / Cc, c = bc % Cc;
    float s = 0.f, s2 = 0.f;
    #pragma unroll
    for (int k = 0; k < 16; k++) {
        s  += p1[(b * 16 + k) * Cc + c];
        s2 += p2[(b * 16 + k) * Cc + c];
    }
    float mu  = s / (float)Ll;
    float var = s2 / (float)Ll - mu * mu;
    mean[bc] = mu;
    rstd[bc] = rsqrtf(var + EPS);
}

// normalize token-major op -> h2 (token-major), tf32-rounded
__global__ void norm2_kernel(const float* __restrict__ op, const float* __restrict__ mean,
                             const float* __restrict__ rstd, const float* __restrict__ g,
                             const float* __restrict__ be, float* __restrict__ out) {
    int i  = blockIdx.x * blockDim.x + threadIdx.x;   // over T*C/4
    int t  = i / (Cc / 4);
    int b  = t / Ll;
    int c4 = (i % (Cc / 4)) * 4;
    const float* mu = mean + b * Cc + c4;
    const float* rs = rstd + b * Cc + c4;
    float4 v = ((const float4*)op)[i];
    v.x = to_tf32((v.x - mu[0]) * rs[0] * g[c4 + 0] + be[c4 + 0]);
    v.y = to_tf32((v.y - mu[1]) * rs[1] * g[c4 + 1] + be[c4 + 1]);
    v.z = to_tf32((v.z - mu[2]) * rs[2] * g[c4 + 2] + be[c4 + 2]);
    v.w = to_tf32((v.w - mu[3]) * rs[3] * g[c4 + 3] + be[c4 + 3]);
    ((float4*)out)[i] = v;
}

// ---------------- final: out[b,c,l] = x[b,c,l] + m[b,l,c] (tiled transpose) ----------
__global__ void add_tr_kernel(const float* __restrict__ x, const float* __restrict__ m,
                              float* __restrict__ out) {
    __shared__ float tile[32][33];
    int l0 = blockIdx.x * 32, c0 = blockIdx.y * 32, b = blockIdx.z;
    #pragma unroll
    for (int j = 0; j < 4; j++) {
        int ll = threadIdx.y + j * 8;
        tile[ll][threadIdx.x] =
            m[((size_t)(b * Ll + l0 + ll)) * Cc + c0 + threadIdx.x];
    }
    __syncthreads();
    #pragma unroll
    for (int j = 0; j < 4; j++) {
        int cc = threadIdx.y + j * 8;
        size_t oi = ((size_t)(b * Cc + c0 + cc)) * Ll + l0 + threadIdx.x;
        out[oi] = x[oi] + tile[threadIdx.x][cc];
    }
}

// ---------------- launch ----------------
extern "C" void kernel_launch(void* const* d_in, const int* in_sizes, int n_in,
                              void* d_out, int out_size) {
    (void)in_sizes; (void)n_in; (void)out_size;
    const float* q   = (const float*)d_in[0];
    const float* x   = (const float*)d_in[1];
    const float* g1  = (const float*)d_in[2];
    const float* b1  = (const float*)d_in[3];
    const float* Wq  = (const float*)d_in[4];
    const float* bq  = (const float*)d_in[5];
    const float* Wk  = (const float*)d_in[6];
    const float* bk  = (const float*)d_in[7];
    const float* Wv  = (const float*)d_in[8];
    const float* bv  = (const float*)d_in[9];
    const float* Wo  = (const float*)d_in[10];
    const float* bo  = (const float*)d_in[11];
    const float* g2  = (const float*)d_in[12];
    const float* b2  = (const float*)d_in[13];
    const float* Wfc = (const float*)d_in[14];
    const float* bfc = (const float*)d_in[15];
    const float* Wpr = (const float*)d_in[16];
    const float* bpr = (const float*)d_in[17];
    float* out = (float*)d_out;

    float *qr, *hn, *Q, *K, *V, *o, *op, *h2, *u, *m;
    float *mean1, *rstd1, *mean2, *rstd2, *p1, *p2;
    float *wq, *wk, *wv, *wo, *wfc, *wpr;
    cudaGetSymbolAddress((void**)&qr,  g_qr);
    cudaGetSymbolAddress((void**)&hn,  g_hn);
    cudaGetSymbolAddress((void**)&Q,   g_Q);
    cudaGetSymbolAddress((void**)&K,   g_K);
    cudaGetSymbolAddress((void**)&V,   g_V);
    cudaGetSymbolAddress((void**)&o,   g_o);
    cudaGetSymbolAddress((void**)&op,  g_op);
    cudaGetSymbolAddress((void**)&h2,  g_h2);
    cudaGetSymbolAddress((void**)&u,   g_u);
    cudaGetSymbolAddress((void**)&m,   g_m);
    cudaGetSymbolAddress((void**)&mean1, g_mean1);
    cudaGetSymbolAddress((void**)&rstd1, g_rstd1);
    cudaGetSymbolAddress((void**)&mean2, g_mean2);
    cudaGetSymbolAddress((void**)&rstd2, g_rstd2);
    cudaGetSymbolAddress((void**)&p1,  g_p1);
    cudaGetSymbolAddress((void**)&p2,  g_p2);
    cudaGetSymbolAddress((void**)&wq,  g_Wq);
    cudaGetSymbolAddress((void**)&wk,  g_Wk);
    cudaGetSymbolAddress((void**)&wv,  g_Wv);
    cudaGetSymbolAddress((void**)&wo,  g_Wo);
    cudaGetSymbolAddress((void**)&wfc, g_Wfc);
    cudaGetSymbolAddress((void**)&wpr, g_Wpr);

    // pre-round (RNA) weights and q to tf32 so cp.async-fed MMA sees unbiased operands
    round4_kernel<<<(T * Cc / 4 + 255) / 256, 256>>>(q, qr, T * Cc / 4);
    round4_kernel<<<(Cc * Cc / 4 + 255) / 256, 256>>>(Wq, wq, Cc * Cc / 4);
    round4_kernel<<<(Cc * Cc / 4 + 255) / 256, 256>>>(Wk, wk, Cc * Cc / 4);
    round4_kernel<<<(Cc * Cc / 4 + 255) / 256, 256>>>(Wv, wv, Cc * Cc / 4);
    round4_kernel<<<(Cc * Cc / 4 + 255) / 256, 256>>>(Wo, wo, Cc * Cc / 4);
    round4_kernel<<<(Cc * C2 / 4 + 255) / 256, 256>>>(Wfc, wfc, Cc * C2 / 4);
    round4_kernel<<<(C2 * Cc / 4 + 255) / 256, 256>>>(Wpr, wpr, C2 * Cc / 4);

    // norm1
    stats1_kernel<<<Bb * Cc, 256>>>(x, mean1, rstd1);
    norm1_kernel<<<(Bb * Cc * Ll / 4) / 256, 256>>>(x, mean1, rstd1, g1, b1, hn);

    // Q/K/V projections (A read directly from channel-major layout)
    gemm_kernel<1, false, false><<<dim3(Cc / BN, T / BM), 256>>>(qr, wq, bq, Q, Cc, Cc);
    gemm_kernel<1, false, false><<<dim3(Cc / BN, T / BM), 256>>>(hn, wk, bk, K, Cc, Cc);
    gemm_kernel<1, false, false><<<dim3(Cc / BN, T / BM), 256>>>(hn, wv, bv, V, Cc, Cc);

    // windowed attention
    attn_kernel<<<T * Hh / 8, 256>>>(Q, K, V, o);

    // output projection
    gemm_kernel<0, false, false><<<dim3(Cc / BN, T / BM), 256>>>(o, wo, bo, op, Cc, Cc);

    // norm2
    stats2_part<<<dim3(16, Bb), Cc>>>(op, p1, p2);
    stats2_fin<<<(Bb * Cc + 255) / 256, 256>>>(p1, p2, mean2, rstd2);
    norm2_kernel<<<(T * Cc / 4) / 256, 256>>>(op, mean2, rstd2, g2, b2, h2);

    // MLP
    gemm_kernel<0, true, true><<<dim3(C2 / BN, T / BM), 256>>>(h2, wfc, bfc, u, Cc, C2);
    gemm_kernel<0, false, false><<<dim3(Cc / BN, T / BM), 256>>>(u, wpr, bpr, m, C2, Cc);

    // residual add + transpose back to (B,C,L)
    add_tr_kernel<<<dim3(Ll / 32, Cc / 32, Bb), dim3(32, 8)>>>(x, m, out);
}